// round 12
// baseline (speedup 1.0000x reference)
#include <cuda_runtime.h>
#include <cuda_fp16.h>

#define N_NODES 100000
#define N_EDGES 1600000
#define F_IN    128
#define HID     64
#define NCLS    16
#define NB_SCAN ((N_NODES + 1023) / 1024)

typedef unsigned long long ull;

// ---------------- f32x2 helpers ----------------
__device__ __forceinline__ ull pack2(float x, float y) {
    ull r; asm("mov.b64 %0, {%1, %2};" : "=l"(r) : "f"(x), "f"(y)); return r;
}
__device__ __forceinline__ void unpack2(ull v, float& x, float& y) {
    asm("mov.b64 {%0, %1}, %2;" : "=f"(x), "=f"(y) : "l"(v));
}
__device__ __forceinline__ ull fma2(ull a, ull b, ull c) {
    ull d; asm("fma.rn.f32x2 %0, %1, %2, %3;" : "=l"(d) : "l"(a), "l"(b), "l"(c)); return d;
}

// ---------------- scratch ----------------
__device__ float g_dinv[N_NODES];
__device__ __align__(8)  int2 g_sd[N_EDGES];    // sanitized (src, dst)
__device__ int   g_cnt[N_NODES];                // ALWAYS zero between launches
__device__ int   g_px[N_NODES];
__device__ int   g_bsum[NB_SCAN];
__device__ int   g_rowptr[N_NODES + 1];
__device__ int   g_fill[N_NODES];
__device__ __align__(16) int2 g_epk[N_EDGES];   // CSR: (src, norm-bits) sorted by dst
__device__ __align__(16) __half2 g_xwh_a[(size_t)N_NODES * (HID / 2)]; // xw layer1 (fp16)
__device__ __align__(16) __half2 g_xwh_b[(size_t)N_NODES * (HID / 2)]; // xw layer2 (fp16)
__device__ __align__(16) float   g_xw [(size_t)N_NODES * NCLS];        // xw layer3 (fp32)

// ---------------- prep: sanitize + histogram (dtype detect per block) ----------------
__global__ void prep_hist_kernel(const void* ei_raw) {
    __shared__ int s_is64;
    if (threadIdx.x == 0) {
        const long long* e64 = (const long long*)ei_raw;
        int ok = 1;
        #pragma unroll
        for (int k = 0; k < 16; k++) {
            long long v = e64[k];
            if (v < 0 || v >= N_NODES) ok = 0;
        }
        s_is64 = ok;
    }
    __syncthreads();
    int e = blockIdx.x * blockDim.x + threadIdx.x;
    if (e >= N_EDGES) return;
    int s, d;
    if (s_is64) {
        const long long* e64 = (const long long*)ei_raw;
        s = (int)e64[e];
        d = (int)e64[(size_t)N_EDGES + e];
    } else {
        const int* e32 = (const int*)ei_raw;
        s = e32[e];
        d = e32[N_EDGES + e];
    }
    if ((unsigned)s >= N_NODES) s = 0;   // never a wild address
    if ((unsigned)d >= N_NODES) d = 0;
    g_sd[e] = make_int2(s, d);
    atomicAdd(&g_cnt[d], 1);
}

// ---------------- 2-level scan ----------------
__global__ void scan1_kernel() {
    __shared__ int s[1024];
    int t = threadIdx.x, b = blockIdx.x;
    int idx = b * 1024 + t;
    int v = (idx < N_NODES) ? g_cnt[idx] : 0;
    s[t] = v; __syncthreads();
    for (int off = 1; off < 1024; off <<= 1) {
        int add = (t >= off) ? s[t - off] : 0;
        __syncthreads();
        s[t] += add;
        __syncthreads();
    }
    int incl = s[t];
    if (idx < N_NODES) g_px[idx] = incl - v;
    if (t == 1023) g_bsum[b] = incl;
}

// rowptr/fill/dinv, block-offset in-kernel; re-zeroes g_cnt for next launch
__global__ void scan3_kernel() {
    __shared__ int s_ofs;
    int t = threadIdx.x;
    int sb = (blockIdx.x * 256) >> 10;
    if (t < 32) {
        int acc = 0;
        for (int i = t; i < sb; i += 32) acc += g_bsum[i];
        #pragma unroll
        for (int off = 16; off > 0; off >>= 1)
            acc += __shfl_xor_sync(0xFFFFFFFFu, acc, off);
        if (t == 0) s_ofs = acc;
    }
    __syncthreads();
    int idx = blockIdx.x * 256 + t;
    if (idx < N_NODES) {
        int base = g_px[idx] + s_ofs;
        g_rowptr[idx] = base;
        g_fill[idx]   = base;
        g_dinv[idx]   = rsqrtf(1.0f + (float)g_cnt[idx]);
        g_cnt[idx]    = 0;                  // self-clean invariant
    }
    if (idx == 0) g_rowptr[N_NODES] = N_EDGES;
}

// scatter edges into CSR order with norm packed alongside src
__global__ void scatter_kernel() {
    int e = blockIdx.x * blockDim.x + threadIdx.x;
    if (e >= N_EDGES) return;
    int2 sd = g_sd[e];
    int pos = atomicAdd(&g_fill[sd.y], 1);
    float nrm = g_dinv[sd.x] * g_dinv[sd.y];
    g_epk[pos] = make_int2(sd.x, __float_as_int(nrm));
}

// ---------------- layer-1 GEMM: g_xwh_a = x @ W1 (f32x2, fp16 out) ----------------
__global__ void __launch_bounds__(256) gemm1_kernel(const float* __restrict__ X,
                                                    const float* __restrict__ W) {
    __shared__ ull    Ws2[F_IN * 32];    // W[k][2c..2c+1] packed
    __shared__ float4 xs4[8][4][F_IN / 4];
    const ull* Wv = (const ull*)W;
    for (int i = threadIdx.x; i < F_IN * 32; i += 256) Ws2[i] = Wv[i];
    __syncthreads();

    const int warp = threadIdx.x >> 5;
    const int lane = threadIdx.x & 31;

    for (int base = (blockIdx.x * 8 + warp) * 4; base < N_NODES;
         base += gridDim.x * 32) {
        #pragma unroll
        for (int n = 0; n < 4; n++) {
            int node = base + n;
            if (node < N_NODES) {
                float* xrow = (float*)&xs4[warp][n][0];
                for (int k = lane; k < F_IN; k += 32)
                    xrow[k] = X[(size_t)node * F_IN + k];
            }
        }
        __syncwarp();

        ull acc[4] = {0ull, 0ull, 0ull, 0ull};
        #pragma unroll 4
        for (int k4 = 0; k4 < F_IN / 4; k4++) {
            float4 xv[4];
            #pragma unroll
            for (int n = 0; n < 4; n++) xv[n] = xs4[warp][n][k4];
            #pragma unroll
            for (int kk = 0; kk < 4; kk++) {
                ull w = Ws2[(k4 * 4 + kk) * 32 + lane];
                float x0 = (kk == 0) ? xv[0].x : (kk == 1) ? xv[0].y : (kk == 2) ? xv[0].z : xv[0].w;
                float x1 = (kk == 0) ? xv[1].x : (kk == 1) ? xv[1].y : (kk == 2) ? xv[1].z : xv[1].w;
                float x2 = (kk == 0) ? xv[2].x : (kk == 1) ? xv[2].y : (kk == 2) ? xv[2].z : xv[2].w;
                float x3 = (kk == 0) ? xv[3].x : (kk == 1) ? xv[3].y : (kk == 2) ? xv[3].z : xv[3].w;
                acc[0] = fma2(w, pack2(x0, x0), acc[0]);
                acc[1] = fma2(w, pack2(x1, x1), acc[1]);
                acc[2] = fma2(w, pack2(x2, x2), acc[2]);
                acc[3] = fma2(w, pack2(x3, x3), acc[3]);
            }
        }

        #pragma unroll
        for (int n = 0; n < 4; n++) {
            int node = base + n;
            if (node < N_NODES) {
                float lo, hi; unpack2(acc[n], lo, hi);
                g_xwh_a[(size_t)node * (HID / 2) + lane] = __floats2half2_rn(lo, hi);
            }
        }
        __syncwarp();
    }
}

// ---------------- pull core: h row (float2 per lane) from fp16 table ----------------
__device__ __forceinline__ ull pull_row(const __half2* __restrict__ xwh,
                                        const float* __restrict__ b,
                                        int node, int lane) {
    float2 bb = ((const float2*)b)[lane];
    float di = g_dinv[node], di2 = di * di;
    float2 xr = __half22float2(xwh[(size_t)node * (HID / 2) + lane]);
    ull acc = pack2(fmaf(xr.x, di2, bb.x), fmaf(xr.y, di2, bb.y));

    int e = g_rowptr[node], end = g_rowptr[node + 1];
    if ((e & 1) && e < end) {        // peel to 16B alignment of g_epk
        int2 p = g_epk[e];
        float2 v = __half22float2(xwh[(size_t)p.x * (HID / 2) + lane]);
        float w = __int_as_float(p.y);
        acc = fma2(pack2(v.x, v.y), pack2(w, w), acc);
        e++;
    }
    for (; e + 7 < end; e += 8) {
        int4 q0 = *(const int4*)&g_epk[e];
        int4 q1 = *(const int4*)&g_epk[e + 2];
        int4 q2 = *(const int4*)&g_epk[e + 4];
        int4 q3 = *(const int4*)&g_epk[e + 6];
        #pragma unroll
        for (int j = 0; j < 4; j++) {
            int4 q = (j == 0) ? q0 : (j == 1) ? q1 : (j == 2) ? q2 : q3;
            float2 v0 = __half22float2(xwh[(size_t)q.x * (HID / 2) + lane]);
            float2 v1 = __half22float2(xwh[(size_t)q.z * (HID / 2) + lane]);
            float w0 = __int_as_float(q.y), w1 = __int_as_float(q.w);
            acc = fma2(pack2(v0.x, v0.y), pack2(w0, w0), acc);
            acc = fma2(pack2(v1.x, v1.y), pack2(w1, w1), acc);
        }
    }
    for (; e < end; e++) {
        int2 p = g_epk[e];
        float2 v = __half22float2(xwh[(size_t)p.x * (HID / 2) + lane]);
        float w = __int_as_float(p.y);
        acc = fma2(pack2(v.x, v.y), pack2(w, w), acc);
    }
    return acc;
}

// ---------------- FUSED: pull layer-1 + GEMM W2 -> g_xwh_b ----------------
__global__ void __launch_bounds__(256) pull_gemm64_kernel(const float* __restrict__ b1,
                                                          const float* __restrict__ W2) {
    __shared__ ull   Ws2[HID * 32];      // W2[k][2c..2c+1] packed (16KB)
    __shared__ float hs[8][HID];         // per-warp relu(h) row
    const ull* Wv = (const ull*)W2;
    for (int i = threadIdx.x; i < HID * 32; i += 256) Ws2[i] = Wv[i];
    __syncthreads();

    int warp = threadIdx.x >> 5, lane = threadIdx.x & 31;
    int node = blockIdx.x * 8 + warp;
    if (node >= N_NODES) return;

    ull h = pull_row(g_xwh_a, b1, node, lane);
    float lo, hi; unpack2(h, lo, hi);
    ((float2*)&hs[warp][0])[lane] = make_float2(fmaxf(lo, 0.0f), fmaxf(hi, 0.0f));
    __syncwarp();

    // per-node GEMM: xw2[2l..2l+1] = sum_k relu_h[k] * W2[k][2l..2l+1]
    ull acc = 0ull;
    const float4* hr = (const float4*)&hs[warp][0];
    #pragma unroll 4
    for (int k4 = 0; k4 < HID / 4; k4++) {
        float4 xv = hr[k4];
        acc = fma2(pack2(xv.x, xv.x), Ws2[(k4 * 4 + 0) * 32 + lane], acc);
        acc = fma2(pack2(xv.y, xv.y), Ws2[(k4 * 4 + 1) * 32 + lane], acc);
        acc = fma2(pack2(xv.z, xv.z), Ws2[(k4 * 4 + 2) * 32 + lane], acc);
        acc = fma2(pack2(xv.w, xv.w), Ws2[(k4 * 4 + 3) * 32 + lane], acc);
    }
    float o0, o1; unpack2(acc, o0, o1);
    g_xwh_b[(size_t)node * (HID / 2) + lane] = __floats2half2_rn(o0, o1);
}

// ---------------- FUSED: pull layer-2 + GEMM W3 -> g_xw (fp32, C=16) ----------------
__global__ void __launch_bounds__(256) pull_gemm16_kernel(const float* __restrict__ b2,
                                                          const float* __restrict__ W3) {
    __shared__ float Ws[HID * NCLS];     // 4KB
    __shared__ float hs[8][HID];
    for (int i = threadIdx.x; i < HID * NCLS; i += 256) Ws[i] = W3[i];
    __syncthreads();

    int warp = threadIdx.x >> 5, lane = threadIdx.x & 31;
    int node = blockIdx.x * 8 + warp;
    if (node >= N_NODES) return;

    ull h = pull_row(g_xwh_b, b2, node, lane);
    float lo, hi; unpack2(h, lo, hi);
    ((float2*)&hs[warp][0])[lane] = make_float2(fmaxf(lo, 0.0f), fmaxf(hi, 0.0f));
    __syncwarp();

    int col = lane & 15, half = lane >> 4;
    float acc = 0.0f;
    #pragma unroll 8
    for (int k = half * (HID / 2); k < (half + 1) * (HID / 2); k++)
        acc = fmaf(hs[warp][k], Ws[k * NCLS + col], acc);
    acc += __shfl_xor_sync(0xFFFFFFFFu, acc, 16);
    if (half == 0) g_xw[(size_t)node * NCLS + col] = acc;
}

// ---------------- final pull, C=16 fp32 ----------------
__global__ void __launch_bounds__(256) pull16_kernel(const float* __restrict__ b,
                                                     float* __restrict__ out) {
    int warp = threadIdx.x >> 5, lane = threadIdx.x & 31;
    int node = blockIdx.x * 8 + warp;
    if (node >= N_NODES) return;

    int col = lane & 15, eh = lane >> 4;
    float di = g_dinv[node];
    float a = 0.0f;
    if (eh == 0) a = fmaf(g_xw[(size_t)node * NCLS + col], di * di, b[col]);

    int start = g_rowptr[node], end = g_rowptr[node + 1];
    for (int e = start + eh; e < end; e += 2) {
        int2 p = g_epk[e];
        a = fmaf(g_xw[(size_t)p.x * NCLS + col], __int_as_float(p.y), a);
    }
    a += __shfl_xor_sync(0xFFFFFFFFu, a, 16);
    if (eh == 0) out[(size_t)node * NCLS + col] = a;
}

// ---------------- launch ----------------
extern "C" void kernel_launch(void* const* d_in, const int* in_sizes, int n_in,
                              void* d_out, int out_size) {
    const float* x  = (const float*)d_in[0];
    const void*  ei = d_in[1];
    const float* W1 = (const float*)d_in[2];
    const float* b1 = (const float*)d_in[3];
    const float* W2 = (const float*)d_in[4];
    const float* b2 = (const float*)d_in[5];
    const float* W3 = (const float*)d_in[6];
    const float* b3 = (const float*)d_in[7];
    float* out = (float*)d_out;

    // One-time side stream + events (fail-safe: serial fallback if creation fails).
    static int          s_mode = -1;
    static cudaStream_t s_side;
    static cudaEvent_t  ev_fork, ev_join;
    if (s_mode < 0) {
        bool ok = (cudaStreamCreateWithFlags(&s_side, cudaStreamNonBlocking) == cudaSuccess)
               && (cudaEventCreateWithFlags(&ev_fork, cudaEventDisableTiming) == cudaSuccess)
               && (cudaEventCreateWithFlags(&ev_join, cudaEventDisableTiming) == cudaSuccess);
        cudaGetLastError();
        s_mode = ok ? 1 : 0;
    }

    const int T = 256;
    const int nb_nodes = (N_NODES + T - 1) / T;
    const int nb_edges = (N_EDGES + T - 1) / T;
    const int nb_pull  = (N_NODES + 7) / 8;
    const int GEMM_GRID = 592;

    if (s_mode == 1) {
        cudaEventRecord(ev_fork, 0);
        cudaStreamWaitEvent(s_side, ev_fork, 0);
        gemm1_kernel<<<GEMM_GRID, T, 0, s_side>>>(x, W1);
        cudaEventRecord(ev_join, s_side);
    }

    // CSR build + normalization (4 launches), concurrent with gemm1
    prep_hist_kernel<<<nb_edges, T>>>(ei);
    scan1_kernel    <<<NB_SCAN, 1024>>>();
    scan3_kernel    <<<nb_nodes, T>>>();
    scatter_kernel  <<<nb_edges, T>>>();

    if (s_mode == 1) {
        cudaStreamWaitEvent(0, ev_join, 0);
    } else {
        gemm1_kernel<<<GEMM_GRID, T>>>(x, W1);   // serial fallback
    }

    // fused layers
    pull_gemm64_kernel<<<nb_pull, T>>>(b1, W2);  // pull1 + gemm2 -> g_xwh_b
    pull_gemm16_kernel<<<nb_pull, T>>>(b2, W3);  // pull2 + gemm3 -> g_xw
    pull16_kernel     <<<nb_pull, T>>>(b3, out); // final aggregation
}

// round 13
// speedup vs baseline: 1.0929x; 1.0929x over previous
#include <cuda_runtime.h>
#include <cuda_fp16.h>

#define N_NODES 100000
#define N_EDGES 1600000
#define F_IN    128
#define HID     64
#define NCLS    16
#define NB_SCAN ((N_NODES + 1023) / 1024)

typedef unsigned long long ull;

// ---------------- f32x2 helpers ----------------
__device__ __forceinline__ ull pack2(float x, float y) {
    ull r; asm("mov.b64 %0, {%1, %2};" : "=l"(r) : "f"(x), "f"(y)); return r;
}
__device__ __forceinline__ void unpack2(ull v, float& x, float& y) {
    asm("mov.b64 {%0, %1}, %2;" : "=f"(x), "=f"(y) : "l"(v));
}
__device__ __forceinline__ ull fma2(ull a, ull b, ull c) {
    ull d; asm("fma.rn.f32x2 %0, %1, %2, %3;" : "=l"(d) : "l"(a), "l"(b), "l"(c)); return d;
}

// ---------------- scratch ----------------
__device__ float g_dinv[N_NODES];
__device__ __align__(8)  int2 g_sd[N_EDGES];    // sanitized (src, dst)
__device__ int   g_cnt[N_NODES];                // ALWAYS zero between launches
__device__ int   g_px[N_NODES];
__device__ int   g_bsum[NB_SCAN];
__device__ int   g_rowptr[N_NODES + 1];
__device__ int   g_fill[N_NODES];
__device__ __align__(16) int2 g_epk[N_EDGES];   // CSR: (src, norm-bits) sorted by dst
__device__ __align__(16) __half2 g_xwh[(size_t)N_NODES * (HID / 2)];  // fp16 GEMM out (layers 1,2)
__device__ __align__(16) float   g_xw [(size_t)N_NODES * NCLS];       // fp32 GEMM out (layer 3)
__device__ __align__(16) float   g_h  [(size_t)N_NODES * HID];        // aggregated hidden

// ---------------- prep: sanitize + histogram (dtype detect per block) ----------------
__global__ void prep_hist_kernel(const void* ei_raw) {
    __shared__ int s_is64;
    if (threadIdx.x == 0) {
        const long long* e64 = (const long long*)ei_raw;
        int ok = 1;
        #pragma unroll
        for (int k = 0; k < 16; k++) {
            long long v = e64[k];
            if (v < 0 || v >= N_NODES) ok = 0;
        }
        s_is64 = ok;
    }
    __syncthreads();
    int e = blockIdx.x * blockDim.x + threadIdx.x;
    if (e >= N_EDGES) return;
    int s, d;
    if (s_is64) {
        const long long* e64 = (const long long*)ei_raw;
        s = (int)e64[e];
        d = (int)e64[(size_t)N_EDGES + e];
    } else {
        const int* e32 = (const int*)ei_raw;
        s = e32[e];
        d = e32[N_EDGES + e];
    }
    if ((unsigned)s >= N_NODES) s = 0;   // never a wild address
    if ((unsigned)d >= N_NODES) d = 0;
    g_sd[e] = make_int2(s, d);
    atomicAdd(&g_cnt[d], 1);
}

// ---------------- 2-level scan ----------------
__global__ void scan1_kernel() {
    __shared__ int s[1024];
    int t = threadIdx.x, b = blockIdx.x;
    int idx = b * 1024 + t;
    int v = (idx < N_NODES) ? g_cnt[idx] : 0;
    s[t] = v; __syncthreads();
    for (int off = 1; off < 1024; off <<= 1) {
        int add = (t >= off) ? s[t - off] : 0;
        __syncthreads();
        s[t] += add;
        __syncthreads();
    }
    int incl = s[t];
    if (idx < N_NODES) g_px[idx] = incl - v;
    if (t == 1023) g_bsum[b] = incl;
}

// rowptr/fill/dinv, block-offset in-kernel; re-zeroes g_cnt for next launch
__global__ void scan3_kernel() {
    __shared__ int s_ofs;
    int t = threadIdx.x;
    int sb = (blockIdx.x * 256) >> 10;
    if (t < 32) {
        int acc = 0;
        for (int i = t; i < sb; i += 32) acc += g_bsum[i];
        #pragma unroll
        for (int off = 16; off > 0; off >>= 1)
            acc += __shfl_xor_sync(0xFFFFFFFFu, acc, off);
        if (t == 0) s_ofs = acc;
    }
    __syncthreads();
    int idx = blockIdx.x * 256 + t;
    if (idx < N_NODES) {
        int base = g_px[idx] + s_ofs;
        g_rowptr[idx] = base;
        g_fill[idx]   = base;
        g_dinv[idx]   = rsqrtf(1.0f + (float)g_cnt[idx]);
        g_cnt[idx]    = 0;                  // self-clean invariant
    }
    if (idx == 0) g_rowptr[N_NODES] = N_EDGES;
}

// scatter edges into CSR order with norm packed alongside src
__global__ void scatter_kernel() {
    int e = blockIdx.x * blockDim.x + threadIdx.x;
    if (e >= N_EDGES) return;
    int2 sd = g_sd[e];
    int pos = atomicAdd(&g_fill[sd.y], 1);
    float nrm = g_dinv[sd.x] * g_dinv[sd.y];
    g_epk[pos] = make_int2(sd.x, __float_as_int(nrm));
}

// ---------------- GEMM C=64 via f32x2, epilogue stores __half2 ----------------
template<int K, bool RELU, bool FROM_H>
__global__ void __launch_bounds__(256) gemm64_kernel(const float* __restrict__ X,
                                                     const float* __restrict__ W) {
    __shared__ ull    Ws2[K * 32];       // W[k][2c..2c+1] packed
    __shared__ float4 xs4[8][4][K / 4];
    const ull* Wv = (const ull*)W;
    for (int i = threadIdx.x; i < K * 32; i += 256) Ws2[i] = Wv[i];
    __syncthreads();

    const int warp = threadIdx.x >> 5;
    const int lane = threadIdx.x & 31;

    for (int base = (blockIdx.x * 8 + warp) * 4; base < N_NODES;
         base += gridDim.x * 32) {
        #pragma unroll
        for (int n = 0; n < 4; n++) {
            int node = base + n;
            if (node < N_NODES) {
                float* xrow = (float*)&xs4[warp][n][0];
                for (int k = lane; k < K; k += 32) {
                    float v = FROM_H ? g_h[(size_t)node * K + k]
                                     : X  [(size_t)node * K + k];
                    if (RELU) v = fmaxf(v, 0.0f);
                    xrow[k] = v;
                }
            }
        }
        __syncwarp();

        ull acc[4] = {0ull, 0ull, 0ull, 0ull};

        #pragma unroll 4
        for (int k4 = 0; k4 < K / 4; k4++) {
            float4 xv[4];
            #pragma unroll
            for (int n = 0; n < 4; n++) xv[n] = xs4[warp][n][k4];
            #pragma unroll
            for (int kk = 0; kk < 4; kk++) {
                ull w = Ws2[(k4 * 4 + kk) * 32 + lane];
                float x0 = (kk == 0) ? xv[0].x : (kk == 1) ? xv[0].y : (kk == 2) ? xv[0].z : xv[0].w;
                float x1 = (kk == 0) ? xv[1].x : (kk == 1) ? xv[1].y : (kk == 2) ? xv[1].z : xv[1].w;
                float x2 = (kk == 0) ? xv[2].x : (kk == 1) ? xv[2].y : (kk == 2) ? xv[2].z : xv[2].w;
                float x3 = (kk == 0) ? xv[3].x : (kk == 1) ? xv[3].y : (kk == 2) ? xv[3].z : xv[3].w;
                acc[0] = fma2(w, pack2(x0, x0), acc[0]);
                acc[1] = fma2(w, pack2(x1, x1), acc[1]);
                acc[2] = fma2(w, pack2(x2, x2), acc[2]);
                acc[3] = fma2(w, pack2(x3, x3), acc[3]);
            }
        }

        #pragma unroll
        for (int n = 0; n < 4; n++) {
            int node = base + n;
            if (node < N_NODES) {
                float lo, hi; unpack2(acc[n], lo, hi);
                g_xwh[(size_t)node * (HID / 2) + lane] = __floats2half2_rn(lo, hi);
            }
        }
        __syncwarp();
    }
}

// ---------------- GEMM C=16 (layer 3, fp32 out) ----------------
template<int K>
__global__ void __launch_bounds__(256) gemm16_kernel(const float* __restrict__ W) {
    __shared__ float Ws[K * NCLS];
    __shared__ float xs[8][4][K];
    for (int i = threadIdx.x; i < K * NCLS; i += 256) Ws[i] = W[i];
    __syncthreads();

    const int warp = threadIdx.x >> 5;
    const int lane = threadIdx.x & 31;
    const int col  = lane & 15;
    const int half = lane >> 4;

    for (int base = (blockIdx.x * 8 + warp) * 4; base < N_NODES;
         base += gridDim.x * 32) {
        #pragma unroll
        for (int n = 0; n < 4; n++) {
            int node = base + n;
            if (node < N_NODES)
                for (int k = lane; k < K; k += 32)
                    xs[warp][n][k] = fmaxf(g_h[(size_t)node * K + k], 0.0f);
        }
        __syncwarp();

        float acc[4] = {0, 0, 0, 0};
        #pragma unroll 4
        for (int k = half * (K / 2); k < (half + 1) * (K / 2); k++) {
            float w = Ws[k * NCLS + col];
            #pragma unroll
            for (int n = 0; n < 4; n++)
                acc[n] = fmaf(xs[warp][n][k], w, acc[n]);
        }
        #pragma unroll
        for (int n = 0; n < 4; n++) {
            acc[n] += __shfl_xor_sync(0xFFFFFFFFu, acc[n], 16);
            int node = base + n;
            if (node < N_NODES && half == 0)
                g_xw[(size_t)node * NCLS + col] = acc[n];
        }
        __syncwarp();
    }
}

// ---------------- pull aggregation: 2 nodes per warp, interleaved chains ----------------
__device__ __forceinline__ ull edge_fma2h(ull acc, int2 p, int lane) {
    float2 v = __half22float2(g_xwh[(size_t)p.x * (HID / 2) + lane]);
    float w = __int_as_float(p.y);
    return fma2(pack2(v.x, v.y), pack2(w, w), acc);
}

__device__ __forceinline__ ull pull_init(const float* __restrict__ b, int node, int lane) {
    float2 bb = ((const float2*)b)[lane];
    float di = g_dinv[node], di2 = di * di;
    float2 xr = __half22float2(g_xwh[(size_t)node * (HID / 2) + lane]);
    return pack2(fmaf(xr.x, di2, bb.x), fmaf(xr.y, di2, bb.y));
}

__global__ void __launch_bounds__(256) pull64_kernel(const float* __restrict__ b) {
    int warp = threadIdx.x >> 5, lane = threadIdx.x & 31;
    int gw = blockIdx.x * 8 + warp;
    int n0 = gw * 2, n1 = gw * 2 + 1;
    if (n0 >= N_NODES) return;
    bool has1 = (n1 < N_NODES);

    int e0 = g_rowptr[n0], end0 = g_rowptr[n0 + 1];
    int e1 = 0, end1 = 0;
    if (has1) { e1 = end0; end1 = g_rowptr[n1 + 1]; }   // rows are contiguous

    ull a0 = pull_init(b, n0, lane);
    ull a1 = has1 ? pull_init(b, n1, lane) : 0ull;

    // interleaved main loop: 4 edges from each node per iteration (2 indep chains)
    while (e0 + 3 < end0 && e1 + 3 < end1) {
        int2 p00 = g_epk[e0], p01 = g_epk[e0 + 1], p02 = g_epk[e0 + 2], p03 = g_epk[e0 + 3];
        int2 p10 = g_epk[e1], p11 = g_epk[e1 + 1], p12 = g_epk[e1 + 2], p13 = g_epk[e1 + 3];
        a0 = edge_fma2h(a0, p00, lane);
        a1 = edge_fma2h(a1, p10, lane);
        a0 = edge_fma2h(a0, p01, lane);
        a1 = edge_fma2h(a1, p11, lane);
        a0 = edge_fma2h(a0, p02, lane);
        a1 = edge_fma2h(a1, p12, lane);
        a0 = edge_fma2h(a0, p03, lane);
        a1 = edge_fma2h(a1, p13, lane);
        e0 += 4; e1 += 4;
    }
    // drain node0
    for (; e0 + 3 < end0; e0 += 4) {
        int2 p0 = g_epk[e0], p1 = g_epk[e0 + 1], p2 = g_epk[e0 + 2], p3 = g_epk[e0 + 3];
        a0 = edge_fma2h(a0, p0, lane);
        a0 = edge_fma2h(a0, p1, lane);
        a0 = edge_fma2h(a0, p2, lane);
        a0 = edge_fma2h(a0, p3, lane);
    }
    for (; e0 < end0; e0++) a0 = edge_fma2h(a0, g_epk[e0], lane);
    // drain node1
    for (; e1 + 3 < end1; e1 += 4) {
        int2 p0 = g_epk[e1], p1 = g_epk[e1 + 1], p2 = g_epk[e1 + 2], p3 = g_epk[e1 + 3];
        a1 = edge_fma2h(a1, p0, lane);
        a1 = edge_fma2h(a1, p1, lane);
        a1 = edge_fma2h(a1, p2, lane);
        a1 = edge_fma2h(a1, p3, lane);
    }
    for (; e1 < end1; e1++) a1 = edge_fma2h(a1, g_epk[e1], lane);

    float lo, hi; unpack2(a0, lo, hi);
    ((float2*)(g_h + (size_t)n0 * HID))[lane] = make_float2(lo, hi);
    if (has1) {
        unpack2(a1, lo, hi);
        ((float2*)(g_h + (size_t)n1 * HID))[lane] = make_float2(lo, hi);
    }
}

// final layer, C=16 fp32: half-warp per edge-parity, shuffle-reduce
__global__ void __launch_bounds__(256) pull16_kernel(const float* __restrict__ b,
                                                     float* __restrict__ out) {
    int warp = threadIdx.x >> 5, lane = threadIdx.x & 31;
    int node = blockIdx.x * 8 + warp;
    if (node >= N_NODES) return;

    int col = lane & 15, eh = lane >> 4;
    float di = g_dinv[node];
    float a = 0.0f;
    if (eh == 0) a = fmaf(g_xw[(size_t)node * NCLS + col], di * di, b[col]);

    int start = g_rowptr[node], end = g_rowptr[node + 1];
    for (int e = start + eh; e < end; e += 2) {
        int2 p = g_epk[e];
        a = fmaf(g_xw[(size_t)p.x * NCLS + col], __int_as_float(p.y), a);
    }
    a += __shfl_xor_sync(0xFFFFFFFFu, a, 16);
    if (eh == 0) out[(size_t)node * NCLS + col] = a;
}

// ---------------- launch ----------------
extern "C" void kernel_launch(void* const* d_in, const int* in_sizes, int n_in,
                              void* d_out, int out_size) {
    const float* x  = (const float*)d_in[0];
    const void*  ei = d_in[1];
    const float* W1 = (const float*)d_in[2];
    const float* b1 = (const float*)d_in[3];
    const float* W2 = (const float*)d_in[4];
    const float* b2 = (const float*)d_in[5];
    const float* W3 = (const float*)d_in[6];
    const float* b3 = (const float*)d_in[7];
    float* out = (float*)d_out;

    // One-time side stream + events (fail-safe: serial fallback if creation fails).
    static int          s_mode = -1;
    static cudaStream_t s_side;
    static cudaEvent_t  ev_fork, ev_join;
    if (s_mode < 0) {
        bool ok = (cudaStreamCreateWithFlags(&s_side, cudaStreamNonBlocking) == cudaSuccess)
               && (cudaEventCreateWithFlags(&ev_fork, cudaEventDisableTiming) == cudaSuccess)
               && (cudaEventCreateWithFlags(&ev_join, cudaEventDisableTiming) == cudaSuccess);
        cudaGetLastError();
        s_mode = ok ? 1 : 0;
    }

    const int T = 256;
    const int nb_nodes  = (N_NODES + T - 1) / T;
    const int nb_edges  = (N_EDGES + T - 1) / T;
    const int nb_pull   = (N_NODES + 7) / 8;       // 1 node/warp kernels
    const int nb_pull2  = (N_NODES + 15) / 16;     // 2 nodes/warp pull64
    const int GEMM_GRID = 592;

    if (s_mode == 1) {
        cudaEventRecord(ev_fork, 0);
        cudaStreamWaitEvent(s_side, ev_fork, 0);
        gemm64_kernel<F_IN, false, false><<<GEMM_GRID, T, 0, s_side>>>(x, W1);
        cudaEventRecord(ev_join, s_side);
    }

    // CSR build + normalization (4 launches), concurrent with gemm1
    prep_hist_kernel<<<nb_edges, T>>>(ei);
    scan1_kernel    <<<NB_SCAN, 1024>>>();
    scan3_kernel    <<<nb_nodes, T>>>();
    scatter_kernel  <<<nb_edges, T>>>();

    if (s_mode == 1) {
        cudaStreamWaitEvent(0, ev_join, 0);
    } else {
        gemm64_kernel<F_IN, false, false><<<GEMM_GRID, T>>>(x, W1);  // serial fallback
    }

    pull64_kernel<<<nb_pull2, T>>>(b1);
    // layer 2
    gemm64_kernel<HID, true, true><<<GEMM_GRID, T>>>(nullptr, W2);
    pull64_kernel<<<nb_pull2, T>>>(b2);
    // layer 3
    gemm16_kernel<HID><<<GEMM_GRID, T>>>(W3);
    pull16_kernel<<<nb_pull, T>>>(b3, out);
}

// round 14
// speedup vs baseline: 1.1485x; 1.0509x over previous
#include <cuda_runtime.h>
#include <cuda_fp16.h>

#define N_NODES 100000
#define N_EDGES 1600000
#define F_IN    128
#define HID     64
#define NCLS    16
#define NB_SCAN ((N_NODES + 1023) / 1024)

typedef unsigned long long ull;

// ---------------- f32x2 helpers ----------------
__device__ __forceinline__ ull pack2(float x, float y) {
    ull r; asm("mov.b64 %0, {%1, %2};" : "=l"(r) : "f"(x), "f"(y)); return r;
}
__device__ __forceinline__ void unpack2(ull v, float& x, float& y) {
    asm("mov.b64 {%0, %1}, %2;" : "=f"(x), "=f"(y) : "l"(v));
}
__device__ __forceinline__ ull fma2(ull a, ull b, ull c) {
    ull d; asm("fma.rn.f32x2 %0, %1, %2, %3;" : "=l"(d) : "l"(a), "l"(b), "l"(c)); return d;
}

// ---------------- scratch ----------------
__device__ float g_dinv[N_NODES];
__device__ int   g_cnt[N_NODES];                // ALWAYS zero between launches
__device__ int   g_px[N_NODES];
__device__ int   g_bsum[NB_SCAN];
__device__ int   g_rowptr[N_NODES + 1];
__device__ int   g_fill[N_NODES];
__device__ __align__(16) int2 g_epk[N_EDGES];   // CSR: (src, norm-bits) sorted by dst
__device__ __align__(16) __half2 g_xwh[(size_t)N_NODES * (HID / 2)];  // fp16 xw (layers 1,2)
__device__ __align__(16) __half2 g_hh [(size_t)N_NODES * (HID / 2)];  // fp16 relu(h)
__device__ __align__(16) float   g_xw [(size_t)N_NODES * NCLS];       // fp32 xw (layer 3)

// ---------------- dtype detect helper (per block, reads 16 values) ----------------
__device__ __forceinline__ int detect_is64(const void* ei_raw) {
    const long long* e64 = (const long long*)ei_raw;
    int ok = 1;
    #pragma unroll
    for (int k = 0; k < 16; k++) {
        long long v = e64[k];
        if (v < 0 || v >= N_NODES) ok = 0;
    }
    return ok;
}

// ---------------- prep: histogram only (read-only pass, 2 edges/thread) ----------------
__global__ void prep_hist_kernel(const void* ei_raw) {
    __shared__ int s_is64;
    if (threadIdx.x == 0) s_is64 = detect_is64(ei_raw);
    __syncthreads();
    int t = blockIdx.x * blockDim.x + threadIdx.x;
    int e = t * 2;
    if (e >= N_EDGES) return;
    int d0, d1;
    if (s_is64) {
        const longlong2* dv = (const longlong2*)((const long long*)ei_raw + N_EDGES);
        longlong2 dd = dv[t];
        d0 = (int)dd.x; d1 = (int)dd.y;
    } else {
        const int2* dv = (const int2*)((const int*)ei_raw + N_EDGES);
        int2 dd = dv[t];
        d0 = dd.x; d1 = dd.y;
    }
    if ((unsigned)d0 >= N_NODES) d0 = 0;
    if ((unsigned)d1 >= N_NODES) d1 = 0;
    atomicAdd(&g_cnt[d0], 1);
    atomicAdd(&g_cnt[d1], 1);
}

// ---------------- 2-level scan ----------------
__global__ void scan1_kernel() {
    __shared__ int s[1024];
    int t = threadIdx.x, b = blockIdx.x;
    int idx = b * 1024 + t;
    int v = (idx < N_NODES) ? g_cnt[idx] : 0;
    s[t] = v; __syncthreads();
    for (int off = 1; off < 1024; off <<= 1) {
        int add = (t >= off) ? s[t - off] : 0;
        __syncthreads();
        s[t] += add;
        __syncthreads();
    }
    int incl = s[t];
    if (idx < N_NODES) g_px[idx] = incl - v;
    if (t == 1023) g_bsum[b] = incl;
}

// rowptr/fill/dinv, block-offset in-kernel; re-zeroes g_cnt for next launch
__global__ void scan3_kernel() {
    __shared__ int s_ofs;
    int t = threadIdx.x;
    int sb = (blockIdx.x * 256) >> 10;
    if (t < 32) {
        int acc = 0;
        for (int i = t; i < sb; i += 32) acc += g_bsum[i];
        #pragma unroll
        for (int off = 16; off > 0; off >>= 1)
            acc += __shfl_xor_sync(0xFFFFFFFFu, acc, off);
        if (t == 0) s_ofs = acc;
    }
    __syncthreads();
    int idx = blockIdx.x * 256 + t;
    if (idx < N_NODES) {
        int base = g_px[idx] + s_ofs;
        g_rowptr[idx] = base;
        g_fill[idx]   = base;
        g_dinv[idx]   = rsqrtf(1.0f + (float)g_cnt[idx]);
        g_cnt[idx]    = 0;                  // self-clean invariant
    }
    if (idx == 0) g_rowptr[N_NODES] = N_EDGES;
}

// scatter edges into CSR order; reads edge_index directly (2 edges/thread)
__global__ void scatter_kernel(const void* ei_raw) {
    __shared__ int s_is64;
    if (threadIdx.x == 0) s_is64 = detect_is64(ei_raw);
    __syncthreads();
    int t = blockIdx.x * blockDim.x + threadIdx.x;
    int e = t * 2;
    if (e >= N_EDGES) return;
    int s0, s1, d0, d1;
    if (s_is64) {
        const longlong2* sv = (const longlong2*)((const long long*)ei_raw);
        const longlong2* dv = (const longlong2*)((const long long*)ei_raw + N_EDGES);
        longlong2 ss = sv[t], dd = dv[t];
        s0 = (int)ss.x; s1 = (int)ss.y; d0 = (int)dd.x; d1 = (int)dd.y;
    } else {
        const int2* sv = (const int2*)((const int*)ei_raw);
        const int2* dv = (const int2*)((const int*)ei_raw + N_EDGES);
        int2 ss = sv[t], dd = dv[t];
        s0 = ss.x; s1 = ss.y; d0 = dd.x; d1 = dd.y;
    }
    if ((unsigned)s0 >= N_NODES) s0 = 0;
    if ((unsigned)s1 >= N_NODES) s1 = 0;
    if ((unsigned)d0 >= N_NODES) d0 = 0;
    if ((unsigned)d1 >= N_NODES) d1 = 0;
    int p0 = atomicAdd(&g_fill[d0], 1);
    g_epk[p0] = make_int2(s0, __float_as_int(g_dinv[s0] * g_dinv[d0]));
    int p1 = atomicAdd(&g_fill[d1], 1);
    g_epk[p1] = make_int2(s1, __float_as_int(g_dinv[s1] * g_dinv[d1]));
}

// ---------------- GEMM C=64 via f32x2, fp16 in (layer2) / fp32 in (layer1), fp16 out ----------------
template<int K, bool FROM_H>
__global__ void __launch_bounds__(256) gemm64_kernel(const float* __restrict__ X,
                                                     const float* __restrict__ W) {
    __shared__ ull    Ws2[K * 32];       // W[k][2c..2c+1] packed
    __shared__ float4 xs4[8][4][K / 4];
    const ull* Wv = (const ull*)W;
    for (int i = threadIdx.x; i < K * 32; i += 256) Ws2[i] = Wv[i];
    __syncthreads();

    const int warp = threadIdx.x >> 5;
    const int lane = threadIdx.x & 31;

    for (int base = (blockIdx.x * 8 + warp) * 4; base < N_NODES;
         base += gridDim.x * 32) {
        #pragma unroll
        for (int n = 0; n < 4; n++) {
            int node = base + n;
            if (node < N_NODES) {
                float* xrow = (float*)&xs4[warp][n][0];
                if (FROM_H) {
                    // K == HID: one half2 per lane covers cols (2l, 2l+1); relu pre-applied
                    float2 v = __half22float2(g_hh[(size_t)node * (HID / 2) + lane]);
                    xrow[2 * lane]     = v.x;
                    xrow[2 * lane + 1] = v.y;
                } else {
                    for (int k = lane; k < K; k += 32)
                        xrow[k] = X[(size_t)node * K + k];
                }
            }
        }
        __syncwarp();

        ull acc[4] = {0ull, 0ull, 0ull, 0ull};

        #pragma unroll 4
        for (int k4 = 0; k4 < K / 4; k4++) {
            float4 xv[4];
            #pragma unroll
            for (int n = 0; n < 4; n++) xv[n] = xs4[warp][n][k4];
            #pragma unroll
            for (int kk = 0; kk < 4; kk++) {
                ull w = Ws2[(k4 * 4 + kk) * 32 + lane];
                float x0 = (kk == 0) ? xv[0].x : (kk == 1) ? xv[0].y : (kk == 2) ? xv[0].z : xv[0].w;
                float x1 = (kk == 0) ? xv[1].x : (kk == 1) ? xv[1].y : (kk == 2) ? xv[1].z : xv[1].w;
                float x2 = (kk == 0) ? xv[2].x : (kk == 1) ? xv[2].y : (kk == 2) ? xv[2].z : xv[2].w;
                float x3 = (kk == 0) ? xv[3].x : (kk == 1) ? xv[3].y : (kk == 2) ? xv[3].z : xv[3].w;
                acc[0] = fma2(w, pack2(x0, x0), acc[0]);
                acc[1] = fma2(w, pack2(x1, x1), acc[1]);
                acc[2] = fma2(w, pack2(x2, x2), acc[2]);
                acc[3] = fma2(w, pack2(x3, x3), acc[3]);
            }
        }

        #pragma unroll
        for (int n = 0; n < 4; n++) {
            int node = base + n;
            if (node < N_NODES) {
                float lo, hi; unpack2(acc[n], lo, hi);
                g_xwh[(size_t)node * (HID / 2) + lane] = __floats2half2_rn(lo, hi);
            }
        }
        __syncwarp();
    }
}

// ---------------- GEMM C=16 (layer 3, fp16 in, fp32 out) ----------------
__global__ void __launch_bounds__(256) gemm16_kernel(const float* __restrict__ W) {
    __shared__ float Ws[HID * NCLS];
    __shared__ float xs[8][4][HID];
    for (int i = threadIdx.x; i < HID * NCLS; i += 256) Ws[i] = W[i];
    __syncthreads();

    const int warp = threadIdx.x >> 5;
    const int lane = threadIdx.x & 31;
    const int col  = lane & 15;
    const int half = lane >> 4;

    for (int base = (blockIdx.x * 8 + warp) * 4; base < N_NODES;
         base += gridDim.x * 32) {
        #pragma unroll
        for (int n = 0; n < 4; n++) {
            int node = base + n;
            if (node < N_NODES) {
                float2 v = __half22float2(g_hh[(size_t)node * (HID / 2) + lane]);
                xs[warp][n][2 * lane]     = v.x;   // relu pre-applied at pull
                xs[warp][n][2 * lane + 1] = v.y;
            }
        }
        __syncwarp();

        float acc[4] = {0, 0, 0, 0};
        #pragma unroll 4
        for (int k = half * (HID / 2); k < (half + 1) * (HID / 2); k++) {
            float w = Ws[k * NCLS + col];
            #pragma unroll
            for (int n = 0; n < 4; n++)
                acc[n] = fmaf(xs[warp][n][k], w, acc[n]);
        }
        #pragma unroll
        for (int n = 0; n < 4; n++) {
            acc[n] += __shfl_xor_sync(0xFFFFFFFFu, acc[n], 16);
            int node = base + n;
            if (node < N_NODES && half == 0)
                g_xw[(size_t)node * NCLS + col] = acc[n];
        }
        __syncwarp();
    }
}

// ---------------- pull aggregation: 2 nodes per warp, interleaved chains ----------------
__device__ __forceinline__ ull edge_fma2h(ull acc, int2 p, int lane) {
    float2 v = __half22float2(g_xwh[(size_t)p.x * (HID / 2) + lane]);
    float w = __int_as_float(p.y);
    return fma2(pack2(v.x, v.y), pack2(w, w), acc);
}

__device__ __forceinline__ ull pull_init(const float* __restrict__ b, int node, int lane) {
    float2 bb = ((const float2*)b)[lane];
    float di = g_dinv[node], di2 = di * di;
    float2 xr = __half22float2(g_xwh[(size_t)node * (HID / 2) + lane]);
    return pack2(fmaf(xr.x, di2, bb.x), fmaf(xr.y, di2, bb.y));
}

__global__ void __launch_bounds__(256) pull64_kernel(const float* __restrict__ b) {
    int warp = threadIdx.x >> 5, lane = threadIdx.x & 31;
    int gw = blockIdx.x * 8 + warp;
    int n0 = gw * 2, n1 = gw * 2 + 1;
    if (n0 >= N_NODES) return;
    bool has1 = (n1 < N_NODES);

    int e0 = g_rowptr[n0], end0 = g_rowptr[n0 + 1];
    int e1 = 0, end1 = 0;
    if (has1) { e1 = end0; end1 = g_rowptr[n1 + 1]; }   // rows are contiguous

    ull a0 = pull_init(b, n0, lane);
    ull a1 = has1 ? pull_init(b, n1, lane) : 0ull;

    // interleaved main loop: 4 edges from each node per iteration (2 indep chains)
    while (e0 + 3 < end0 && e1 + 3 < end1) {
        int2 p00 = g_epk[e0], p01 = g_epk[e0 + 1], p02 = g_epk[e0 + 2], p03 = g_epk[e0 + 3];
        int2 p10 = g_epk[e1], p11 = g_epk[e1 + 1], p12 = g_epk[e1 + 2], p13 = g_epk[e1 + 3];
        a0 = edge_fma2h(a0, p00, lane);
        a1 = edge_fma2h(a1, p10, lane);
        a0 = edge_fma2h(a0, p01, lane);
        a1 = edge_fma2h(a1, p11, lane);
        a0 = edge_fma2h(a0, p02, lane);
        a1 = edge_fma2h(a1, p12, lane);
        a0 = edge_fma2h(a0, p03, lane);
        a1 = edge_fma2h(a1, p13, lane);
        e0 += 4; e1 += 4;
    }
    for (; e0 + 3 < end0; e0 += 4) {
        int2 p0 = g_epk[e0], p1 = g_epk[e0 + 1], p2 = g_epk[e0 + 2], p3 = g_epk[e0 + 3];
        a0 = edge_fma2h(a0, p0, lane);
        a0 = edge_fma2h(a0, p1, lane);
        a0 = edge_fma2h(a0, p2, lane);
        a0 = edge_fma2h(a0, p3, lane);
    }
    for (; e0 < end0; e0++) a0 = edge_fma2h(a0, g_epk[e0], lane);
    for (; e1 + 3 < end1; e1 += 4) {
        int2 p0 = g_epk[e1], p1 = g_epk[e1 + 1], p2 = g_epk[e1 + 2], p3 = g_epk[e1 + 3];
        a1 = edge_fma2h(a1, p0, lane);
        a1 = edge_fma2h(a1, p1, lane);
        a1 = edge_fma2h(a1, p2, lane);
        a1 = edge_fma2h(a1, p3, lane);
    }
    for (; e1 < end1; e1++) a1 = edge_fma2h(a1, g_epk[e1], lane);

    float lo, hi; unpack2(a0, lo, hi);
    g_hh[(size_t)n0 * (HID / 2) + lane] =
        __floats2half2_rn(fmaxf(lo, 0.0f), fmaxf(hi, 0.0f));   // relu fused here
    if (has1) {
        unpack2(a1, lo, hi);
        g_hh[(size_t)n1 * (HID / 2) + lane] =
            __floats2half2_rn(fmaxf(lo, 0.0f), fmaxf(hi, 0.0f));
    }
}

// final layer, C=16 fp32: half-warp per edge-parity, shuffle-reduce
__global__ void __launch_bounds__(256) pull16_kernel(const float* __restrict__ b,
                                                     float* __restrict__ out) {
    int warp = threadIdx.x >> 5, lane = threadIdx.x & 31;
    int node = blockIdx.x * 8 + warp;
    if (node >= N_NODES) return;

    int col = lane & 15, eh = lane >> 4;
    float di = g_dinv[node];
    float a = 0.0f;
    if (eh == 0) a = fmaf(g_xw[(size_t)node * NCLS + col], di * di, b[col]);

    int start = g_rowptr[node], end = g_rowptr[node + 1];
    for (int e = start + eh; e < end; e += 2) {
        int2 p = g_epk[e];
        a = fmaf(g_xw[(size_t)p.x * NCLS + col], __int_as_float(p.y), a);
    }
    a += __shfl_xor_sync(0xFFFFFFFFu, a, 16);
    if (eh == 0) out[(size_t)node * NCLS + col] = a;
}

// ---------------- launch ----------------
extern "C" void kernel_launch(void* const* d_in, const int* in_sizes, int n_in,
                              void* d_out, int out_size) {
    const float* x  = (const float*)d_in[0];
    const void*  ei = d_in[1];
    const float* W1 = (const float*)d_in[2];
    const float* b1 = (const float*)d_in[3];
    const float* W2 = (const float*)d_in[4];
    const float* b2 = (const float*)d_in[5];
    const float* W3 = (const float*)d_in[6];
    const float* b3 = (const float*)d_in[7];
    float* out = (float*)d_out;

    // One-time side stream + events (fail-safe: serial fallback if creation fails).
    static int          s_mode = -1;
    static cudaStream_t s_side;
    static cudaEvent_t  ev_fork, ev_join;
    if (s_mode < 0) {
        bool ok = (cudaStreamCreateWithFlags(&s_side, cudaStreamNonBlocking) == cudaSuccess)
               && (cudaEventCreateWithFlags(&ev_fork, cudaEventDisableTiming) == cudaSuccess)
               && (cudaEventCreateWithFlags(&ev_join, cudaEventDisableTiming) == cudaSuccess);
        cudaGetLastError();
        s_mode = ok ? 1 : 0;
    }

    const int T = 256;
    const int nb_nodes  = (N_NODES + T - 1) / T;
    const int nb_edges2 = (N_EDGES / 2 + T - 1) / T;   // 2 edges per thread
    const int nb_pull   = (N_NODES + 7) / 8;
    const int nb_pull2  = (N_NODES + 15) / 16;
    const int GEMM_GRID = 592;

    if (s_mode == 1) {
        cudaEventRecord(ev_fork, 0);
        cudaStreamWaitEvent(s_side, ev_fork, 0);
        gemm64_kernel<F_IN, false><<<GEMM_GRID, T, 0, s_side>>>(x, W1);
        cudaEventRecord(ev_join, s_side);
    }

    // CSR build + normalization (4 launches), concurrent with gemm1
    prep_hist_kernel<<<nb_edges2, T>>>(ei);
    scan1_kernel    <<<NB_SCAN, 1024>>>();
    scan3_kernel    <<<nb_nodes, T>>>();
    scatter_kernel  <<<nb_edges2, T>>>(ei);

    if (s_mode == 1) {
        cudaStreamWaitEvent(0, ev_join, 0);
    } else {
        gemm64_kernel<F_IN, false><<<GEMM_GRID, T>>>(x, W1);  // serial fallback
    }

    pull64_kernel<<<nb_pull2, T>>>(b1);
    // layer 2
    gemm64_kernel<HID, true><<<GEMM_GRID, T>>>(nullptr, W2);
    pull64_kernel<<<nb_pull2, T>>>(b2);
    // layer 3
    gemm16_kernel<<<GEMM_GRID, T>>>(W3);
    pull16_kernel<<<nb_pull, T>>>(b3, out);
}